// round 10
// baseline (speedup 1.0000x reference)
#include <cuda_runtime.h>
#include <cuda_bf16.h>
#include <cstdint>

#define DIM     64
#define NMAX    262144
#define NLMAX   1024
#define TAU     2.0f
#define UPITCH  36          // uints per bf16 tile row: 32 data + 4 pad (bank-clean)

__device__ float g_csq[NLMAX];
__device__ int   g_ncand;
__device__ int   g_nfull;
__device__ int4  g_cand[NMAX];   // (row, c1, c2, c3<0 = absent)
__device__ int   g_full[NMAX];

typedef unsigned long long u64;

// Packed fp32x2 FMA (FFMA2) for the exact full-rescue pass.
__device__ __forceinline__ u64 ffma2(u64 a, u64 b, u64 c) {
    u64 d;
    asm("fma.rn.f32x2 %0, %1, %2, %3;" : "=l"(d) : "l"(a), "l"(b), "l"(c));
    return d;
}
__device__ __forceinline__ float2 unpack2(u64 v) {
    float2 f;
    asm("mov.b64 {%0, %1}, %2;" : "=f"(f.x), "=f"(f.y) : "l"(v));
    return f;
}

// bf16 tensor-core MMA, m16n8k16 (2x FLOP/instr vs tf32 m16n8k8).
__device__ __forceinline__ void mma_bf16(float c[4], const uint32_t a[4],
                                         const uint32_t b[2]) {
    asm volatile(
        "mma.sync.aligned.m16n8k16.row.col.f32.bf16.bf16.f32 "
        "{%0,%1,%2,%3}, {%4,%5,%6,%7}, {%8,%9}, {%0,%1,%2,%3};"
        : "+f"(c[0]), "+f"(c[1]), "+f"(c[2]), "+f"(c[3])
        : "r"(a[0]), "r"(a[1]), "r"(a[2]), "r"(a[3]), "r"(b[0]), "r"(b[1]));
}

__device__ __forceinline__ uint32_t packbf2(float x, float y) {
    __nv_bfloat162 h = __floats2bfloat162_rn(x, y);   // lo = x, hi = y
    return *reinterpret_cast<uint32_t*>(&h);
}

// Sorted insert into a per-row top-4 (strict '<' keeps first occurrence).
__device__ __forceinline__ void ins4(float d, int ci, float* m, int* ii) {
    if (d < m[3]) {
        m[3] = d; ii[3] = ci;
        if (m[3] < m[2]) {
            float tf = m[2]; m[2] = m[3]; m[3] = tf;
            int   ti = ii[2]; ii[2] = ii[3]; ii[3] = ti;
            if (m[2] < m[1]) {
                tf = m[1]; m[1] = m[2]; m[2] = tf;
                ti = ii[1]; ii[1] = ii[2]; ii[2] = ti;
                if (m[1] < m[0]) {
                    tf = m[0]; m[0] = m[1]; m[1] = tf;
                    ti = ii[0]; ii[0] = ii[1]; ii[1] = ti;
                }
            }
        }
    }
}

// ---------------------------------------------------------------------------
// Kernel 0: centroid squared norms (warp per row) + counter reset.
// ---------------------------------------------------------------------------
__global__ void csq_kernel(const float* __restrict__ cents) {
    if (blockIdx.x == 0 && threadIdx.x == 0) { g_ncand = 0; g_nfull = 0; }
    int w    = (blockIdx.x * blockDim.x + threadIdx.x) >> 5;
    int lane = threadIdx.x & 31;
    if (w < NLMAX) {
        float2 v = reinterpret_cast<const float2*>(cents + (size_t)w * DIM)[lane];
        float s = v.x * v.x + v.y * v.y;
        #pragma unroll
        for (int off = 16; off > 0; off >>= 1)
            s += __shfl_xor_sync(0xffffffffu, s, off);
        if (lane == 0) g_csq[w] = s;
    }
}

// ---------------------------------------------------------------------------
// Kernel 1: bf16 mma.sync assignment + top-4 margins + fused gather.
// CTA tile M=128, 8 tiles of 128 cents (double-buffered bf16 smem), K=64.
// 8 warps as 4(M) x 2(N); warp tile 32x64 -> 2x8 m16n8k16 fragments.
// ---------------------------------------------------------------------------
#define UA_OFF   0
#define UB_OFF   18432               // two buffers of 128*36*4 B
#define SCSQ_OFF 55296
#define MRGD_OFF 59392               // float [2][128][4]
#define MRGI_OFF 63488               // int   [2][128][4]
#define SBI_OFF  67584               // int   [128]
#define SMEMB    68096

__global__ __launch_bounds__(256, 1)
void assign_mma_kernel(const float* __restrict__ vecs,
                       const float* __restrict__ cents,
                       float* __restrict__ out) {
    extern __shared__ char smem[];
    uint32_t* uA    = reinterpret_cast<uint32_t*>(smem + UA_OFF);
    uint32_t* uB    = reinterpret_cast<uint32_t*>(smem + UB_OFF);
    float*    scsq  = reinterpret_cast<float*>(smem + SCSQ_OFF);
    float*    smrgd = reinterpret_cast<float*>(smem + MRGD_OFF);
    int*      smrgi = reinterpret_cast<int*>(smem + MRGI_OFF);
    int*      sbi   = reinterpret_cast<int*>(smem + SBI_OFF);

    const int tid  = threadIdx.x;
    const int lane = tid & 31;
    const int wid  = tid >> 5;
    const int g    = lane >> 2;
    const int tig  = lane & 3;
    const int moff = (wid >> 1) * 32;
    const int noff = (wid & 1) * 64;
    const int vbase = blockIdx.x * 128;

    // A tile: fp32 -> bf16x2, padded rows (UPITCH=36 -> conflict-free frags).
    #pragma unroll
    for (int k = 0; k < 8; k++) {
        int idx = tid + 256 * k;
        int r = idx >> 4, c4 = idx & 15;
        float4 v = reinterpret_cast<const float4*>(vecs)[(size_t)(vbase + r) * 16 + c4];
        uint2 u = make_uint2(packbf2(v.x, v.y), packbf2(v.z, v.w));
        *reinterpret_cast<uint2*>(&uA[r * UPITCH + c4 * 2]) = u;
    }
    // Prefetch B tile 0 into regs.
    float4 pf[8];
    #pragma unroll
    for (int k = 0; k < 8; k++) {
        int idx = tid + 256 * k;
        int r = idx >> 4, c4 = idx & 15;
        pf[k] = reinterpret_cast<const float4*>(cents)[(size_t)r * 16 + c4];
    }
    #pragma unroll
    for (int k = 0; k < 4; k++) scsq[tid + 256 * k] = g_csq[tid + 256 * k];
    // Store tile 0 into buffer 0.
    #pragma unroll
    for (int k = 0; k < 8; k++) {
        int idx = tid + 256 * k;
        int r = idx >> 4, c4 = idx & 15;
        uint2 u = make_uint2(packbf2(pf[k].x, pf[k].y), packbf2(pf[k].z, pf[k].w));
        *reinterpret_cast<uint2*>(&uB[r * UPITCH + c4 * 2]) = u;
    }
    __syncthreads();

    // Per-thread top-4 for 4 row-slots: s=mt*2+hi -> row moff+mt*16+hi*8+g.
    float m[4][4];
    int   ii[4][4];
    #pragma unroll
    for (int s = 0; s < 4; s++)
        #pragma unroll
        for (int q = 0; q < 4; q++) { m[s][q] = 3.4e38f; ii[s][q] = 0; }

    for (int t = 0; t < 8; t++) {
        if (t < 7) {   // prefetch next tile (LDG overlaps this tile's MMAs)
            #pragma unroll
            for (int k = 0; k < 8; k++) {
                int idx = tid + 256 * k;
                int r = idx >> 4, c4 = idx & 15;
                pf[k] = reinterpret_cast<const float4*>(cents)
                            [(size_t)((t + 1) * 128 + r) * 16 + c4];
            }
        }

        const uint32_t* sB = uB + (t & 1) * (128 * UPITCH);

        float c[2][8][4];
        #pragma unroll
        for (int mt = 0; mt < 2; mt++)
            #pragma unroll
            for (int nf = 0; nf < 8; nf++)
                #pragma unroll
                for (int q = 0; q < 4; q++) c[mt][nf][q] = 0.f;

        #pragma unroll
        for (int ks = 0; ks < 4; ks++) {          // K16 steps
            const int u0 = ks * 8 + tig;
            uint32_t a[2][4], b[8][2];
            #pragma unroll
            for (int mt = 0; mt < 2; mt++) {
                int ra = moff + mt * 16 + g;
                a[mt][0] = uA[ra * UPITCH + u0];
                a[mt][1] = uA[(ra + 8) * UPITCH + u0];
                a[mt][2] = uA[ra * UPITCH + u0 + 4];
                a[mt][3] = uA[(ra + 8) * UPITCH + u0 + 4];
            }
            #pragma unroll
            for (int nf = 0; nf < 8; nf++) {
                int rb = noff + nf * 8 + g;
                b[nf][0] = sB[rb * UPITCH + u0];
                b[nf][1] = sB[rb * UPITCH + u0 + 4];
            }
            #pragma unroll
            for (int mt = 0; mt < 2; mt++)
                #pragma unroll
                for (int nf = 0; nf < 8; nf++)
                    mma_bf16(c[mt][nf], a[mt], b[nf]);
        }

        // Epilogue: d2 = csq - 2*dot, top-4 insert.
        #pragma unroll
        for (int nf = 0; nf < 8; nf++) {
            int   cb  = t * 128 + noff + nf * 8 + 2 * tig;
            float cs0 = scsq[cb], cs1 = scsq[cb + 1];
            #pragma unroll
            for (int mt = 0; mt < 2; mt++) {
                ins4(fmaf(-2.f, c[mt][nf][0], cs0), cb,     m[mt*2],   ii[mt*2]);
                ins4(fmaf(-2.f, c[mt][nf][1], cs1), cb + 1, m[mt*2],   ii[mt*2]);
                ins4(fmaf(-2.f, c[mt][nf][2], cs0), cb,     m[mt*2+1], ii[mt*2+1]);
                ins4(fmaf(-2.f, c[mt][nf][3], cs1), cb + 1, m[mt*2+1], ii[mt*2+1]);
            }
        }

        if (t < 7) {   // store prefetched tile into the other buffer
            uint32_t* dst = uB + ((t + 1) & 1) * (128 * UPITCH);
            #pragma unroll
            for (int k = 0; k < 8; k++) {
                int idx = tid + 256 * k;
                int r = idx >> 4, c4 = idx & 15;
                uint2 u = make_uint2(packbf2(pf[k].x, pf[k].y),
                                     packbf2(pf[k].z, pf[k].w));
                *reinterpret_cast<uint2*>(&dst[r * UPITCH + c4 * 2]) = u;
            }
        }
        __syncthreads();
    }

    // Quad merge across tig lanes (same rows, different centroid columns).
    #pragma unroll
    for (int off = 1; off <= 2; off <<= 1) {
        #pragma unroll
        for (int s = 0; s < 4; s++) {
            float om[4]; int oi[4];
            #pragma unroll
            for (int q = 0; q < 4; q++) {
                om[q] = __shfl_xor_sync(0xffffffffu, m[s][q], off);
                oi[q] = __shfl_xor_sync(0xffffffffu, ii[s][q], off);
            }
            #pragma unroll
            for (int q = 0; q < 4; q++) ins4(om[q], oi[q], m[s], ii[s]);
        }
    }
    const int half = wid & 1;
    if (tig == 0) {
        #pragma unroll
        for (int s = 0; s < 4; s++) {
            int row = moff + (s >> 1) * 16 + (s & 1) * 8 + g;
            #pragma unroll
            for (int q = 0; q < 4; q++) {
                smrgd[(half * 128 + row) * 4 + q] = m[s][q];
                smrgi[(half * 128 + row) * 4 + q] = ii[s][q];
            }
        }
    }
    __syncthreads();

    // Merge the two N-halves; classify; emit rescue work.
    if (tid < 128) {
        float M[4]; int I[4];
        #pragma unroll
        for (int q = 0; q < 4; q++) {
            M[q] = smrgd[tid * 4 + q];
            I[q] = smrgi[tid * 4 + q];
        }
        #pragma unroll
        for (int q = 0; q < 4; q++)
            ins4(smrgd[(128 + tid) * 4 + q], smrgi[(128 + tid) * 4 + q], M, I);
        sbi[tid] = I[0];

        bool amb  = (M[1] - M[0] < TAU);
        bool fullf = (M[3] - M[0] < TAU);       // can't certify candidate set
        bool candf = amb && !fullf;

        unsigned balc = __ballot_sync(0xffffffffu, candf);
        if (balc) {
            int ldr = __ffs(balc) - 1;
            int base = 0;
            if (lane == ldr) base = atomicAdd(&g_ncand, __popc(balc));
            base = __shfl_sync(0xffffffffu, base, ldr);
            if (candf) {
                int pos = base + __popc(balc & ((1u << lane) - 1));
                g_cand[pos] = make_int4(vbase + tid, I[0], I[1],
                                        (M[2] - M[0] < TAU) ? I[2] : -1);
            }
        }
        unsigned balf = __ballot_sync(0xffffffffu, fullf);
        if (balf) {
            int ldr = __ffs(balf) - 1;
            int base = 0;
            if (lane == ldr) base = atomicAdd(&g_nfull, __popc(balf));
            base = __shfl_sync(0xffffffffu, base, ldr);
            if (fullf) {
                int pos = base + __popc(balf & ((1u << lane) - 1));
                g_full[pos] = vbase + tid;
            }
        }
    }
    __syncthreads();

    // Fused gather: coalesced write of (approx) winning centroid rows.
    #pragma unroll
    for (int k = 0; k < 8; k++) {
        int idx = tid + 256 * k;
        int r = idx >> 4, c4 = idx & 15;
        reinterpret_cast<float4*>(out)[(size_t)vbase * 16 + idx] =
            reinterpret_cast<const float4*>(cents)[sbi[r] * 16 + c4];
    }
}

// ---------------------------------------------------------------------------
// Kernel 2: exact fp32 check among 2-3 certified candidates per ambiguous row.
// ---------------------------------------------------------------------------
__global__ void cand_kernel(const float* __restrict__ vecs,
                            const float* __restrict__ cents,
                            float* __restrict__ out) {
    const int cnt = g_ncand;
    int idx = blockIdx.x * 256 + threadIdx.x;
    if (idx >= cnt) return;
    int4 e = g_cand[idx];
    float4 v[16];
    const float4* vr = reinterpret_cast<const float4*>(vecs) + (size_t)e.x * 16;
    #pragma unroll
    for (int k = 0; k < 16; k++) v[k] = vr[k];

    float bd = 3.4e38f;
    int   bi = 0x7fffffff;
    int cand[3] = {e.y, e.z, e.w};
    #pragma unroll
    for (int j = 0; j < 3; j++) {
        int ci = cand[j];
        if (ci >= 0) {
            const float4* cr = reinterpret_cast<const float4*>(cents) + ci * 16;
            float s0 = 0.f, s1 = 0.f, s2 = 0.f, s3 = 0.f;
            #pragma unroll
            for (int k = 0; k < 16; k++) {
                float4 cv = cr[k];
                s0 = fmaf(v[k].x, cv.x, s0);
                s1 = fmaf(v[k].y, cv.y, s1);
                s2 = fmaf(v[k].z, cv.z, s2);
                s3 = fmaf(v[k].w, cv.w, s3);
            }
            float d2 = fmaf(-2.f, (s0 + s1) + (s2 + s3), g_csq[ci]);
            if (d2 < bd || (d2 == bd && ci < bi)) { bd = d2; bi = ci; }
        }
    }
    const float4* cr = reinterpret_cast<const float4*>(cents) + bi * 16;
    float4* orow = reinterpret_cast<float4*>(out) + (size_t)e.x * 16;
    #pragma unroll
    for (int k = 0; k < 16; k++) orow[k] = cr[k];
}

// ---------------------------------------------------------------------------
// Kernel 3: exact-fp32 full rescan for uncertifiable rows (FFMA2-blocked).
// ---------------------------------------------------------------------------
#define BM   128
#define BN   64
#define TV   8
#define TCN  4
#define PAD  68

__global__ __launch_bounds__(256, 2)
void rescue_kernel(const float* __restrict__ vecs,
                   const float* __restrict__ cents,
                   float* __restrict__ out, int nlist) {
    const int cnt = g_nfull;
    if (blockIdx.x * BM >= cnt) return;

    extern __shared__ float sm[];
    float* svec  = sm;                        // [BM][PAD]
    float* scent = svec + BM * PAD;           // [BN][PAD]
    float* scsq  = scent + BN * PAD;          // [BN]
    float* sredd = scsq + BN;                 // [16][BM]
    int*   sredi = (int*)(sredd + 16 * BM);   // [16][BM]
    int*   srow  = sredi + 16 * BM;           // [BM]

    const int tid = threadIdx.x;
    const int tx  = tid & 15;
    const int ty  = tid >> 4;
    const int base = blockIdx.x * BM;

    if (tid < BM) {
        int p = base + tid;
        srow[tid] = g_full[p < cnt ? p : cnt - 1];
    }
    __syncthreads();

    #pragma unroll
    for (int k = 0; k < 8; k++) {
        int idx = tid + 256 * k;
        int r = idx >> 4, c4 = idx & 15;
        float4 val = reinterpret_cast<const float4*>(vecs)[(size_t)srow[r] * 16 + c4];
        *reinterpret_cast<float4*>(&svec[r * PAD + c4 * 4]) = val;
    }

    float bestd[TV];
    int   besti[TV];
    #pragma unroll
    for (int j = 0; j < TV; j++) { bestd[j] = 3.4e38f; besti[j] = 0; }

    for (int t = 0; t < nlist; t += BN) {
        __syncthreads();
        #pragma unroll
        for (int k = 0; k < 4; k++) {
            int idx = tid + 256 * k;
            int r = idx >> 4, c4 = idx & 15;
            float4 val = reinterpret_cast<const float4*>(cents)[(size_t)(t + r) * 16 + c4];
            *reinterpret_cast<float4*>(&scent[r * PAD + c4 * 4]) = val;
        }
        if (tid < BN) scsq[tid] = g_csq[t + tid];
        __syncthreads();

        u64 acc[TV][TCN];
        #pragma unroll
        for (int j = 0; j < TV; j++)
            #pragma unroll
            for (int c = 0; c < TCN; c++) acc[j][c] = 0ull;

        #pragma unroll
        for (int k4 = 0; k4 < DIM / 4; k4++) {
            ulonglong2 vv[TV], cc[TCN];
            #pragma unroll
            for (int j = 0; j < TV; j++)
                vv[j] = *reinterpret_cast<const ulonglong2*>(
                            &svec[(tx + 16 * j) * PAD + k4 * 4]);
            #pragma unroll
            for (int c = 0; c < TCN; c++)
                cc[c] = *reinterpret_cast<const ulonglong2*>(
                            &scent[(ty + 16 * c) * PAD + k4 * 4]);
            #pragma unroll
            for (int j = 0; j < TV; j++)
                #pragma unroll
                for (int c = 0; c < TCN; c++) {
                    acc[j][c] = ffma2(vv[j].x, cc[c].x, acc[j][c]);
                    acc[j][c] = ffma2(vv[j].y, cc[c].y, acc[j][c]);
                }
        }

        #pragma unroll
        for (int c = 0; c < TCN; c++) {
            int   ci = t + ty + 16 * c;
            float cs = scsq[ty + 16 * c];
            #pragma unroll
            for (int j = 0; j < TV; j++) {
                float2 f  = unpack2(acc[j][c]);
                float  d2 = fmaf(-2.f, f.x + f.y, cs);
                if (d2 < bestd[j]) { bestd[j] = d2; besti[j] = ci; }
            }
        }
    }

    #pragma unroll
    for (int j = 0; j < TV; j++) {
        int v = tx + 16 * j;
        sredd[ty * BM + v] = bestd[j];
        sredi[ty * BM + v] = besti[j];
    }
    __syncthreads();
    if (tid < BM) {
        float bd = sredd[tid];
        int   bi2 = sredi[tid];
        #pragma unroll
        for (int r = 1; r < 16; r++) {
            float d  = sredd[r * BM + tid];
            int   i2 = sredi[r * BM + tid];
            if (d < bd || (d == bd && i2 < bi2)) { bd = d; bi2 = i2; }
        }
        const float4* crow = reinterpret_cast<const float4*>(cents) + bi2 * 16;
        float4*       orow = reinterpret_cast<float4*>(out) + (size_t)srow[tid] * 16;
        #pragma unroll
        for (int j = 0; j < 16; j++) orow[j] = crow[j];
    }
}

// ---------------------------------------------------------------------------
extern "C" void kernel_launch(void* const* d_in, const int* in_sizes, int n_in,
                              void* d_out, int out_size) {
    const float* vecs  = (const float*)d_in[0];
    const float* cents = (const float*)d_in[1];
    float*       out   = (float*)d_out;

    const int n     = in_sizes[0] / DIM;   // 262144
    const int nlist = in_sizes[1] / DIM;   // 1024

    const int rescue_smem = (BM * PAD + BN * PAD + BN + 16 * BM) * 4
                          + 16 * BM * 4 + BM * 4;
    cudaFuncSetAttribute(assign_mma_kernel,
                         cudaFuncAttributeMaxDynamicSharedMemorySize, SMEMB);
    cudaFuncSetAttribute(rescue_kernel,
                         cudaFuncAttributeMaxDynamicSharedMemorySize, rescue_smem);

    csq_kernel<<<128, 256>>>(cents);
    assign_mma_kernel<<<n / 128, 256, SMEMB>>>(vecs, cents, out);
    cand_kernel<<<NMAX / 256, 256>>>(vecs, cents, out);
    rescue_kernel<<<NMAX / BM, 256, rescue_smem>>>(vecs, cents, out, nlist);
}

// round 11
// speedup vs baseline: 2.8676x; 2.8676x over previous
#include <cuda_runtime.h>
#include <cuda_fp16.h>
#include <cstdint>

#define DIM     64
#define NMAX    262144
#define NLMAX   1024
#define TAU     0.3f
#define UPITCH  36          // uints per f16 tile row: 32 data + 4 pad (bank-clean)

__device__ float g_csq[NLMAX];
__device__ int   g_nrescue;
__device__ int   g_rescue[NMAX];

typedef unsigned long long u64;

// Packed fp32x2 FMA (FFMA2) for the exact full-rescue pass.
__device__ __forceinline__ u64 ffma2(u64 a, u64 b, u64 c) {
    u64 d;
    asm("fma.rn.f32x2 %0, %1, %2, %3;" : "=l"(d) : "l"(a), "l"(b), "l"(c));
    return d;
}
__device__ __forceinline__ float2 unpack2(u64 v) {
    float2 f;
    asm("mov.b64 {%0, %1}, %2;" : "=f"(f.x), "=f"(f.y) : "l"(v));
    return f;
}

// fp16 tensor-core MMA, m16n8k16 with fp32 accumulate (2x MACs/instr vs tf32).
__device__ __forceinline__ void mma_f16(float c[4], const uint32_t a[4],
                                        const uint32_t b[2]) {
    asm volatile(
        "mma.sync.aligned.m16n8k16.row.col.f32.f16.f16.f32 "
        "{%0,%1,%2,%3}, {%4,%5,%6,%7}, {%8,%9}, {%0,%1,%2,%3};"
        : "+f"(c[0]), "+f"(c[1]), "+f"(c[2]), "+f"(c[3])
        : "r"(a[0]), "r"(a[1]), "r"(a[2]), "r"(a[3]), "r"(b[0]), "r"(b[1]));
}

__device__ __forceinline__ uint32_t packhf2(float x, float y) {
    __half2 h = __floats2half2_rn(x, y);   // lo = x, hi = y
    return *reinterpret_cast<uint32_t*>(&h);
}

// ---------------------------------------------------------------------------
// Kernel 0: centroid squared norms (warp per row) + counter reset.
// ---------------------------------------------------------------------------
__global__ void csq_kernel(const float* __restrict__ cents) {
    if (blockIdx.x == 0 && threadIdx.x == 0) g_nrescue = 0;
    int w    = (blockIdx.x * blockDim.x + threadIdx.x) >> 5;
    int lane = threadIdx.x & 31;
    if (w < NLMAX) {
        float2 v = reinterpret_cast<const float2*>(cents + (size_t)w * DIM)[lane];
        float s = v.x * v.x + v.y * v.y;
        #pragma unroll
        for (int off = 16; off > 0; off >>= 1)
            s += __shfl_xor_sync(0xffffffffu, s, off);
        if (lane == 0) g_csq[w] = s;
    }
}

// ---------------------------------------------------------------------------
// Kernel 1: fp16 mma.sync assignment + top-2 margins + fused gather.
// CTA tile M=128, 8 tiles of 128 cents (double-buffered f16 smem), K=64.
// 8 warps as 4(M) x 2(N); warp tile 32x64 -> 2x8 m16n8k16 fragments.
// d2_approx = csq - 2*dot. Rows with min2-min1 < TAU -> exact fp32 rescue.
// ---------------------------------------------------------------------------
#define UA_OFF   0
#define UB_OFF   18432               // two buffers of 128*36*4 B
#define SCSQ_OFF 55296
#define RED1_OFF 59392               // float [2][128]
#define RED2_OFF 60416               // float [2][128]
#define REDI_OFF 61440               // int   [2][128]
#define SBI_OFF  62464               // int   [128]
#define SMEMB    62976

__global__ __launch_bounds__(256, 2)
void assign_mma_kernel(const float* __restrict__ vecs,
                       const float* __restrict__ cents,
                       float* __restrict__ out) {
    extern __shared__ char smem[];
    uint32_t* uA    = reinterpret_cast<uint32_t*>(smem + UA_OFF);
    uint32_t* uB    = reinterpret_cast<uint32_t*>(smem + UB_OFF);
    float*    scsq  = reinterpret_cast<float*>(smem + SCSQ_OFF);
    float*    sred1 = reinterpret_cast<float*>(smem + RED1_OFF);
    float*    sred2 = reinterpret_cast<float*>(smem + RED2_OFF);
    int*      sredi = reinterpret_cast<int*>(smem + REDI_OFF);
    int*      sbi   = reinterpret_cast<int*>(smem + SBI_OFF);

    const int tid  = threadIdx.x;
    const int lane = tid & 31;
    const int wid  = tid >> 5;
    const int g    = lane >> 2;
    const int tig  = lane & 3;
    const int moff = (wid >> 1) * 32;
    const int noff = (wid & 1) * 64;
    const int vbase = blockIdx.x * 128;

    // A tile: fp32 -> f16x2, padded rows (UPITCH=36 -> conflict-free frags).
    #pragma unroll
    for (int k = 0; k < 8; k++) {
        int idx = tid + 256 * k;
        int r = idx >> 4, c4 = idx & 15;
        float4 v = reinterpret_cast<const float4*>(vecs)[(size_t)(vbase + r) * 16 + c4];
        uint2 u = make_uint2(packhf2(v.x, v.y), packhf2(v.z, v.w));
        *reinterpret_cast<uint2*>(&uA[r * UPITCH + c4 * 2]) = u;
    }
    // Prefetch B tile 0 into regs.
    float4 pf[8];
    #pragma unroll
    for (int k = 0; k < 8; k++) {
        int idx = tid + 256 * k;
        int r = idx >> 4, c4 = idx & 15;
        pf[k] = reinterpret_cast<const float4*>(cents)[(size_t)r * 16 + c4];
    }
    #pragma unroll
    for (int k = 0; k < 4; k++) scsq[tid + 256 * k] = g_csq[tid + 256 * k];
    // Store tile 0 into buffer 0.
    #pragma unroll
    for (int k = 0; k < 8; k++) {
        int idx = tid + 256 * k;
        int r = idx >> 4, c4 = idx & 15;
        uint2 u = make_uint2(packhf2(pf[k].x, pf[k].y), packhf2(pf[k].z, pf[k].w));
        *reinterpret_cast<uint2*>(&uB[r * UPITCH + c4 * 2]) = u;
    }
    __syncthreads();

    // Per-thread state for 4 row-slots: s=mt*2+hi -> row moff+mt*16+hi*8+g.
    float m1[4], m2[4];
    int   bi[4];
    #pragma unroll
    for (int s = 0; s < 4; s++) { m1[s] = 3.4e38f; m2[s] = 3.4e38f; bi[s] = 0; }

    for (int t = 0; t < 8; t++) {
        if (t < 7) {   // prefetch next tile (LDG overlaps this tile's MMAs)
            #pragma unroll
            for (int k = 0; k < 8; k++) {
                int idx = tid + 256 * k;
                int r = idx >> 4, c4 = idx & 15;
                pf[k] = reinterpret_cast<const float4*>(cents)
                            [(size_t)((t + 1) * 128 + r) * 16 + c4];
            }
        }

        const uint32_t* sB = uB + (t & 1) * (128 * UPITCH);

        float c[2][8][4];
        #pragma unroll
        for (int mt = 0; mt < 2; mt++)
            #pragma unroll
            for (int nf = 0; nf < 8; nf++)
                #pragma unroll
                for (int q = 0; q < 4; q++) c[mt][nf][q] = 0.f;

        #pragma unroll
        for (int ks = 0; ks < 4; ks++) {          // K16 steps
            const int u0 = ks * 8 + tig;
            uint32_t a[2][4], b[8][2];
            #pragma unroll
            for (int mt = 0; mt < 2; mt++) {
                int ra = moff + mt * 16 + g;
                a[mt][0] = uA[ra * UPITCH + u0];
                a[mt][1] = uA[(ra + 8) * UPITCH + u0];
                a[mt][2] = uA[ra * UPITCH + u0 + 4];
                a[mt][3] = uA[(ra + 8) * UPITCH + u0 + 4];
            }
            #pragma unroll
            for (int nf = 0; nf < 8; nf++) {
                int rb = noff + nf * 8 + g;
                b[nf][0] = sB[rb * UPITCH + u0];
                b[nf][1] = sB[rb * UPITCH + u0 + 4];
            }
            #pragma unroll
            for (int mt = 0; mt < 2; mt++)
                #pragma unroll
                for (int nf = 0; nf < 8; nf++)
                    mma_f16(c[mt][nf], a[mt], b[nf]);
        }

        // Epilogue: d2 = csq - 2*dot, running top-2 update.
        #pragma unroll
        for (int nf = 0; nf < 8; nf++) {
            int   cb  = t * 128 + noff + nf * 8 + 2 * tig;
            float cs0 = scsq[cb], cs1 = scsq[cb + 1];
            #pragma unroll
            for (int mt = 0; mt < 2; mt++) {
                const int s0 = mt * 2, s1 = mt * 2 + 1;
                float d;
                d = fmaf(-2.f, c[mt][nf][0], cs0);
                if (d < m1[s0]) { m2[s0] = m1[s0]; m1[s0] = d; bi[s0] = cb; }
                else            { m2[s0] = fminf(m2[s0], d); }
                d = fmaf(-2.f, c[mt][nf][1], cs1);
                if (d < m1[s0]) { m2[s0] = m1[s0]; m1[s0] = d; bi[s0] = cb + 1; }
                else            { m2[s0] = fminf(m2[s0], d); }
                d = fmaf(-2.f, c[mt][nf][2], cs0);
                if (d < m1[s1]) { m2[s1] = m1[s1]; m1[s1] = d; bi[s1] = cb; }
                else            { m2[s1] = fminf(m2[s1], d); }
                d = fmaf(-2.f, c[mt][nf][3], cs1);
                if (d < m1[s1]) { m2[s1] = m1[s1]; m1[s1] = d; bi[s1] = cb + 1; }
                else            { m2[s1] = fminf(m2[s1], d); }
            }
        }

        if (t < 7) {   // store prefetched tile into the other buffer
            uint32_t* dst = uB + ((t + 1) & 1) * (128 * UPITCH);
            #pragma unroll
            for (int k = 0; k < 8; k++) {
                int idx = tid + 256 * k;
                int r = idx >> 4, c4 = idx & 15;
                uint2 u = make_uint2(packhf2(pf[k].x, pf[k].y),
                                     packhf2(pf[k].z, pf[k].w));
                *reinterpret_cast<uint2*>(&dst[r * UPITCH + c4 * 2]) = u;
            }
        }
        __syncthreads();
    }

    // Quad reduction (lanes sharing g hold the same 4 rows; tig differs).
    #pragma unroll
    for (int off = 1; off <= 2; off <<= 1) {
        #pragma unroll
        for (int s = 0; s < 4; s++) {
            float om1 = __shfl_xor_sync(0xffffffffu, m1[s], off);
            float om2 = __shfl_xor_sync(0xffffffffu, m2[s], off);
            int   oi  = __shfl_xor_sync(0xffffffffu, bi[s], off);
            bool better = (om1 < m1[s]) || (om1 == m1[s] && oi < bi[s]);
            m2[s] = fminf(fminf(m2[s], om2), fmaxf(m1[s], om1));
            m1[s] = fminf(m1[s], om1);
            if (better) bi[s] = oi;
        }
    }
    const int half = wid & 1;
    if (tig == 0) {
        #pragma unroll
        for (int s = 0; s < 4; s++) {
            int row = moff + (s >> 1) * 16 + (s & 1) * 8 + g;
            sred1[half * 128 + row] = m1[s];
            sred2[half * 128 + row] = m2[s];
            sredi[half * 128 + row] = bi[s];
        }
    }
    __syncthreads();
    if (tid < 128) {
        float a1 = sred1[tid],   b1 = sred1[128 + tid];
        float a2 = sred2[tid],   b2 = sred2[128 + tid];
        int   ai = sredi[tid],   bx = sredi[128 + tid];
        bool  bb = (b1 < a1) || (b1 == a1 && bx < ai);
        float g1 = fminf(a1, b1);
        float g2 = fminf(fminf(a2, b2), fmaxf(a1, b1));
        sbi[tid] = bb ? bx : ai;
        if (g2 - g1 < TAU) {
            int p = atomicAdd(&g_nrescue, 1);
            g_rescue[p] = vbase + tid;
        }
    }
    __syncthreads();

    // Fused gather: coalesced write of (approx) winning centroid rows.
    #pragma unroll
    for (int k = 0; k < 8; k++) {
        int idx = tid + 256 * k;
        int r = idx >> 4, c4 = idx & 15;
        reinterpret_cast<float4*>(out)[(size_t)vbase * 16 + idx] =
            reinterpret_cast<const float4*>(cents)[sbi[r] * 16 + c4];
    }
}

// ---------------------------------------------------------------------------
// Kernel 2: exact-fp32 full rescan for ambiguous rows (FFMA2-blocked).
// Overwrites the output rows it re-resolves.
// ---------------------------------------------------------------------------
#define BM   128
#define BN   64
#define TV   8
#define TCN  4
#define PAD  68

__global__ __launch_bounds__(256, 2)
void rescue_kernel(const float* __restrict__ vecs,
                   const float* __restrict__ cents,
                   float* __restrict__ out, int nlist) {
    const int cnt = g_nrescue;
    if (blockIdx.x * BM >= cnt) return;

    extern __shared__ float sm[];
    float* svec  = sm;                        // [BM][PAD]
    float* scent = svec + BM * PAD;           // [BN][PAD]
    float* scsq  = scent + BN * PAD;          // [BN]
    float* sredd = scsq + BN;                 // [16][BM]
    int*   sredi = (int*)(sredd + 16 * BM);   // [16][BM]
    int*   srow  = sredi + 16 * BM;           // [BM]

    const int tid = threadIdx.x;
    const int tx  = tid & 15;
    const int ty  = tid >> 4;
    const int base = blockIdx.x * BM;

    if (tid < BM) {
        int p = base + tid;
        srow[tid] = g_rescue[p < cnt ? p : cnt - 1];
    }
    __syncthreads();

    #pragma unroll
    for (int k = 0; k < 8; k++) {
        int idx = tid + 256 * k;
        int r = idx >> 4, c4 = idx & 15;
        float4 val = reinterpret_cast<const float4*>(vecs)[(size_t)srow[r] * 16 + c4];
        *reinterpret_cast<float4*>(&svec[r * PAD + c4 * 4]) = val;
    }

    float bestd[TV];
    int   besti[TV];
    #pragma unroll
    for (int j = 0; j < TV; j++) { bestd[j] = 3.4e38f; besti[j] = 0; }

    for (int t = 0; t < nlist; t += BN) {
        __syncthreads();
        #pragma unroll
        for (int k = 0; k < 4; k++) {
            int idx = tid + 256 * k;
            int r = idx >> 4, c4 = idx & 15;
            float4 val = reinterpret_cast<const float4*>(cents)[(size_t)(t + r) * 16 + c4];
            *reinterpret_cast<float4*>(&scent[r * PAD + c4 * 4]) = val;
        }
        if (tid < BN) scsq[tid] = g_csq[t + tid];
        __syncthreads();

        u64 acc[TV][TCN];
        #pragma unroll
        for (int j = 0; j < TV; j++)
            #pragma unroll
            for (int c = 0; c < TCN; c++) acc[j][c] = 0ull;

        #pragma unroll
        for (int k4 = 0; k4 < DIM / 4; k4++) {
            ulonglong2 vv[TV], cc[TCN];
            #pragma unroll
            for (int j = 0; j < TV; j++)
                vv[j] = *reinterpret_cast<const ulonglong2*>(
                            &svec[(tx + 16 * j) * PAD + k4 * 4]);
            #pragma unroll
            for (int c = 0; c < TCN; c++)
                cc[c] = *reinterpret_cast<const ulonglong2*>(
                            &scent[(ty + 16 * c) * PAD + k4 * 4]);
            #pragma unroll
            for (int j = 0; j < TV; j++)
                #pragma unroll
                for (int c = 0; c < TCN; c++) {
                    acc[j][c] = ffma2(vv[j].x, cc[c].x, acc[j][c]);
                    acc[j][c] = ffma2(vv[j].y, cc[c].y, acc[j][c]);
                }
        }

        #pragma unroll
        for (int c = 0; c < TCN; c++) {
            int   ci = t + ty + 16 * c;
            float cs = scsq[ty + 16 * c];
            #pragma unroll
            for (int j = 0; j < TV; j++) {
                float2 f  = unpack2(acc[j][c]);
                float  d2 = fmaf(-2.f, f.x + f.y, cs);
                if (d2 < bestd[j]) { bestd[j] = d2; besti[j] = ci; }
            }
        }
    }

    #pragma unroll
    for (int j = 0; j < TV; j++) {
        int v = tx + 16 * j;
        sredd[ty * BM + v] = bestd[j];
        sredi[ty * BM + v] = besti[j];
    }
    __syncthreads();
    if (tid < BM) {
        float bd = sredd[tid];
        int   bi2 = sredi[tid];
        #pragma unroll
        for (int r = 1; r < 16; r++) {
            float d  = sredd[r * BM + tid];
            int   i2 = sredi[r * BM + tid];
            if (d < bd || (d == bd && i2 < bi2)) { bd = d; bi2 = i2; }
        }
        const float4* crow = reinterpret_cast<const float4*>(cents) + bi2 * 16;
        float4*       orow = reinterpret_cast<float4*>(out) + (size_t)srow[tid] * 16;
        #pragma unroll
        for (int j = 0; j < 16; j++) orow[j] = crow[j];
    }
}

// ---------------------------------------------------------------------------
extern "C" void kernel_launch(void* const* d_in, const int* in_sizes, int n_in,
                              void* d_out, int out_size) {
    const float* vecs  = (const float*)d_in[0];
    const float* cents = (const float*)d_in[1];
    float*       out   = (float*)d_out;

    const int n     = in_sizes[0] / DIM;   // 262144
    const int nlist = in_sizes[1] / DIM;   // 1024

    const int rescue_smem = (BM * PAD + BN * PAD + BN + 16 * BM) * 4
                          + 16 * BM * 4 + BM * 4;
    cudaFuncSetAttribute(assign_mma_kernel,
                         cudaFuncAttributeMaxDynamicSharedMemorySize, SMEMB);
    cudaFuncSetAttribute(rescue_kernel,
                         cudaFuncAttributeMaxDynamicSharedMemorySize, rescue_smem);

    csq_kernel<<<128, 256>>>(cents);
    assign_mma_kernel<<<n / 128, 256, SMEMB>>>(vecs, cents, out);
    rescue_kernel<<<NMAX / BM, 256, rescue_smem>>>(vecs, cents, out, nlist);
}